// round 14
// baseline (speedup 1.0000x reference)
#include <cuda_runtime.h>
#include <cuda_fp16.h>
#include <cstdint>

#define NROWS 4096
#define DIM   512
#define KH    8
#define WPC   4      /* rows (warps) per attention CTA */
#define MAXW  96     /* max neighbors per row (mean 42, sd 6.4 -> 8 sigma) */

// ---------------- scratch (device globals; no allocations allowed) ----------
__device__ __align__(256) float   g_Z[(size_t)NROWS * DIM];   // Z fp32 [i][c]
__device__ __align__(256) __half  g_Hh[NROWS * DIM];          // H fp16 hi [i][d]
__device__ __align__(256) __half  g_Hl[NROWS * DIM];          // H fp16 lo
__device__ __align__(256) __half  g_A1h[NROWS * DIM];         // Zagg fp16 hi [i][c]
__device__ __align__(256) __half  g_A1l[NROWS * DIM];         // Zagg fp16 lo
__device__ __align__(256) __half  g_B0[DIM * DIM];            // gemm0 B fp16: [c][d]
__device__ __align__(256) __half  g_B1[DIM * DIM];            // gemm1 B fp16: [d][c]
__device__ int g_cnt[NROWS];
__device__ int g_nbrL[NROWS][MAXW];

// ---------------- helpers ----------------------------------------------------
__device__ __forceinline__ uint32_t smem_to_u32(const void* p) {
    uint32_t a;
    asm("{ .reg .u64 t; cvta.to.shared.u64 t, %1; cvt.u32.u64 %0, t; }" : "=r"(a) : "l"(p));
    return a;
}
__device__ __forceinline__ void ldsm_x4(uint32_t* r, uint32_t addr) {
    asm volatile("ldmatrix.sync.aligned.m8n8.x4.shared.b16 {%0,%1,%2,%3}, [%4];"
                 : "=r"(r[0]), "=r"(r[1]), "=r"(r[2]), "=r"(r[3]) : "r"(addr));
}
__device__ __forceinline__ void mma16816(float* c, const uint32_t* a, const uint32_t* b) {
    asm volatile(
        "mma.sync.aligned.m16n8k16.row.col.f32.f16.f16.f32 "
        "{%0,%1,%2,%3}, {%4,%5,%6,%7}, {%8,%9}, {%0,%1,%2,%3};"
        : "+f"(c[0]), "+f"(c[1]), "+f"(c[2]), "+f"(c[3])
        : "r"(a[0]), "r"(a[1]), "r"(a[2]), "r"(a[3]), "r"(b[0]), "r"(b[1]));
}
__device__ __forceinline__ void cp16(uint32_t saddr, const void* g) {
    asm volatile("cp.async.cg.shared.global [%0], [%1], 16;" :: "r"(saddr), "l"(g));
}
#define CP_COMMIT() asm volatile("cp.async.commit_group;" ::: "memory")
#define CP_WAIT1()  asm volatile("cp.async.wait_group 1;" ::: "memory")
#define CP_WAIT0()  asm volatile("cp.async.wait_group 0;" ::: "memory")

__device__ __forceinline__ void split_f16(float v, __half& h, __half& l) {
    h = __float2half_rn(v);
    l = __float2half_rn(v - __half2float(h));
}

// ---------------- adjacency scan -> compact neighbor lists ------------------
__global__ void __launch_bounds__(256)
scan_kernel(const float* __restrict__ adj) {
    __shared__ int wsum[8], wpre[8];
    const int i = blockIdx.x;
    const int tid = threadIdx.x, lane = tid & 31, wid = tid >> 5;
    const float4* arow = (const float4*)(adj + (size_t)i * NROWS);

    float4 v0 = arow[tid * 4 + 0];
    float4 v1 = arow[tid * 4 + 1];
    float4 v2 = arow[tid * 4 + 2];
    float4 v3 = arow[tid * 4 + 3];
    uint32_t flags = 0;
    flags |= (v0.x != 0.f ?     1u : 0u) | (v0.y != 0.f ?     2u : 0u) |
             (v0.z != 0.f ?     4u : 0u) | (v0.w != 0.f ?     8u : 0u);
    flags |= (v1.x != 0.f ?  0x10u : 0u) | (v1.y != 0.f ?  0x20u : 0u) |
             (v1.z != 0.f ?  0x40u : 0u) | (v1.w != 0.f ?  0x80u : 0u);
    flags |= (v2.x != 0.f ? 0x100u : 0u) | (v2.y != 0.f ? 0x200u : 0u) |
             (v2.z != 0.f ? 0x400u : 0u) | (v2.w != 0.f ? 0x800u : 0u);
    flags |= (v3.x != 0.f ? 0x1000u : 0u) | (v3.y != 0.f ? 0x2000u : 0u) |
             (v3.z != 0.f ? 0x4000u : 0u) | (v3.w != 0.f ? 0x8000u : 0u);
    int cnt = __popc(flags);

    int pos = cnt;
#pragma unroll
    for (int o = 1; o < 32; o <<= 1) {
        int t = __shfl_up_sync(0xffffffffu, pos, o);
        if (lane >= o) pos += t;
    }
    if (lane == 31) wsum[wid] = pos;
    __syncthreads();
    if (tid == 0) {
        int a = 0;
#pragma unroll
        for (int w = 0; w < 8; w++) { wpre[w] = a; a += wsum[w]; }
        g_cnt[i] = a < MAXW ? a : MAXW;
    }
    __syncthreads();
    int p = wpre[wid] + pos - cnt;          // exclusive prefix across CTA
    uint32_t m = flags;
    while (m) {
        int b = __ffs(m) - 1; m &= m - 1;
        if (p < MAXW) g_nbrL[i][p] = tid * 16 + b;
        p++;
    }
}

// ---------------- repack U -> B0 (transposed) and B1 (copy), smem-tiled -----
__global__ void __launch_bounds__(256)
repack_kernel(const float* __restrict__ U) {
    __shared__ __half tile[32][33];
    const int kt = blockIdx.x;        // r-tile: 0..1
    const int dt = blockIdx.y;        // d-tile: 0..15
    const int k  = blockIdx.z;        // head:   0..7
    const int tx = threadIdx.x & 31, ty = threadIdx.x >> 5;   // 32 x 8

    const float* Uk = U + (size_t)k * 32768;
#pragma unroll
    for (int i = 0; i < 4; i++) {
        int dd = ty + i * 8;
        int d  = dt * 32 + dd;
        int r  = kt * 32 + tx;
        __half h = __float2half_rn(Uk[d * 64 + r]);
        g_B1[(d << 9) + k * 64 + r] = h;           // coalesced
        tile[dd][tx] = h;
    }
    __syncthreads();
#pragma unroll
    for (int i = 0; i < 4; i++) {
        int cc = ty + i * 8;
        int c  = k * 64 + kt * 32 + cc;
        g_B0[(c << 9) + dt * 32 + tx] = tile[tx][cc];   // coalesced
    }
}

// ---------------- split H into fp16 hi/lo ------------------------------------
__global__ void convert_h_kernel(const float* __restrict__ H) {
    int i4 = blockIdx.x * 256 + threadIdx.x;
    if (i4 >= NROWS * DIM / 4) return;
    float4 v = ((const float4*)H)[i4];
    __half h0, l0, h1, l1, h2, l2, h3, l3;
    split_f16(v.x, h0, l0); split_f16(v.y, h1, l1);
    split_f16(v.z, h2, l2); split_f16(v.w, h3, l3);
    int b = i4 * 4;
    g_Hh[b] = h0; g_Hh[b + 1] = h1; g_Hh[b + 2] = h2; g_Hh[b + 3] = h3;
    g_Hl[b] = l0; g_Hl[b + 1] = l1; g_Hl[b + 2] = l2; g_Hl[b + 3] = l3;
}

// ---------------- zero orth scalar -------------------------------------------
__global__ void zero_kernel(float* p) { *p = 0.f; }

// ---------------- HMMA GEMM: 64x128 CTA tile, K=512, fp16 2-term split ------
// TWO-stage cp.async pipeline (known-good config).
#define GEMM_STAGE 32768            /* Ah 8K | Al 8K | B 16K */
#define GEMM_SMEM  (2 * GEMM_STAGE)
template <int MODE>
__global__ void __launch_bounds__(256, 2)
hmma_gemm(float* __restrict__ Cout, const float* __restrict__ Hin,
          const float* __restrict__ thr) {
    extern __shared__ __align__(1024) char smem[];
    const uint32_t sb = smem_to_u32(smem);
    const int tid  = threadIdx.x;
    const int wid  = tid >> 5, lane = tid & 31;
    const int bm   = blockIdx.y * 64, bn = blockIdx.x * 128;
    const int wm   = (wid >> 2) * 32;
    const int wn   = (wid & 3) * 32;

    const __half* Ah = (MODE == 0) ? g_Hh : g_A1h;
    const __half* Al = (MODE == 0) ? g_Hl : g_A1l;
    const __half* Bm = (MODE == 0) ? g_B0 : g_B1;

    float acc[2][4][4];
#pragma unroll
    for (int a = 0; a < 2; a++)
#pragma unroll
        for (int b = 0; b < 4; b++)
#pragma unroll
            for (int e = 0; e < 4; e++) acc[a][b][e] = 0.f;

    const int aRow = (lane & 15);
    const int aKb  = (lane >> 4) * 16;
    const int bRow = (lane & 7) + ((lane >> 4) << 3);
    const int bKb  = ((lane >> 3) & 1) * 16;

#define STAGE(KC, BUF) do {                                                   \
        const int k0s = (KC) * 64;                                            \
        uint32_t sbase = sb + (BUF) * GEMM_STAGE;                             \
        _Pragma("unroll")                                                     \
        for (int it = 0; it < 2; it++) {                                      \
            int idx = it * 256 + tid;                                         \
            int row = idx >> 3, c16 = idx & 7;                                \
            uint32_t off = (uint32_t)row * 128 + c16 * 16;                    \
            uint32_t sw  = off ^ ((off >> 3) & 0x70);                         \
            size_t g = (size_t)(bm + row) * DIM + k0s + c16 * 8;              \
            cp16(sbase +        sw, Ah + g);                                  \
            cp16(sbase + 8192 + sw, Al + g);                                  \
        }                                                                     \
        _Pragma("unroll")                                                     \
        for (int it = 0; it < 4; it++) {                                      \
            int idx = it * 256 + tid;                                         \
            int row = idx >> 3, c16 = idx & 7;                                \
            uint32_t off = (uint32_t)row * 128 + c16 * 16;                    \
            uint32_t sw  = off ^ ((off >> 3) & 0x70);                         \
            size_t g = (size_t)(bn + row) * DIM + k0s + c16 * 8;              \
            cp16(sbase + 16384 + sw, Bm + g);                                 \
        }                                                                     \
    } while (0)

    STAGE(0, 0); CP_COMMIT();

    for (int kc = 0; kc < 8; kc++) {
        if (kc < 7) { STAGE(kc + 1, (kc + 1) & 1); CP_COMMIT(); CP_WAIT1(); }
        else        { CP_WAIT0(); }
        __syncthreads();
        const uint32_t sbase = sb + (kc & 1) * GEMM_STAGE;
#pragma unroll
        for (int ks = 0; ks < 4; ks++) {
            uint32_t bf[2][4];
#pragma unroll
            for (int g2 = 0; g2 < 2; g2++) {
                uint32_t off = (uint32_t)(wn + g2 * 16 + bRow) * 128 + ks * 32 + bKb;
                uint32_t sw  = off ^ ((off >> 3) & 0x70);
                ldsm_x4(bf[g2], sbase + 16384 + sw);
            }
#pragma unroll
            for (int mf = 0; mf < 2; mf++) {
                uint32_t ah[4], al[4];
                uint32_t off = (uint32_t)(wm + mf * 16 + aRow) * 128 + ks * 32 + aKb;
                uint32_t sw  = off ^ ((off >> 3) & 0x70);
                ldsm_x4(ah, sbase +        sw);
                ldsm_x4(al, sbase + 8192 + sw);
#pragma unroll
                for (int nf = 0; nf < 4; nf++) {
                    const uint32_t* bp = &bf[nf >> 1][(nf & 1) * 2];
                    mma16816(acc[mf][nf], ah, bp);
                    mma16816(acc[mf][nf], al, bp);
                }
            }
        }
        __syncthreads();
    }
#undef STAGE

#pragma unroll
    for (int mf = 0; mf < 2; mf++) {
#pragma unroll
        for (int nf = 0; nf < 4; nf++) {
            int row = bm + wm + mf * 16 + (lane >> 2);
            int col = bn + wn + nf * 8 + (lane & 3) * 2;
            const float* c = acc[mf][nf];
            if (MODE == 0) {
                *(float2*)&g_Z[(size_t)row * DIM + col]       = make_float2(c[0], c[1]);
                *(float2*)&g_Z[(size_t)(row + 8) * DIM + col] = make_float2(c[2], c[3]);
            } else {
                float2 h0 = *(const float2*)&Hin[(size_t)row * DIM + col];
                float2 h1 = *(const float2*)&Hin[(size_t)(row + 8) * DIM + col];
                float2 t  = *(const float2*)&thr[col];
                float2 o0 = make_float2(fmaxf(h0.x + 0.5f * c[0] - t.x, 0.f),
                                        fmaxf(h0.y + 0.5f * c[1] - t.y, 0.f));
                float2 o1 = make_float2(fmaxf(h1.x + 0.5f * c[2] - t.x, 0.f),
                                        fmaxf(h1.y + 0.5f * c[3] - t.y, 0.f));
                *(float2*)&Cout[(size_t)row * DIM + col]       = o0;
                *(float2*)&Cout[(size_t)(row + 8) * DIM + col] = o1;
            }
        }
    }
}

// ---------------- warp-per-row attention, 2-deep prefetch, higher occupancy -
__global__ void __launch_bounds__(128, 6)
attn_kernel() {
    __shared__ int s_nbr[WPC][MAXW];

    const int wid = threadIdx.x >> 5, lane = threadIdx.x & 31;
    const int i = blockIdx.x * WPC + wid;
    const int n = g_cnt[i];

    for (int t = lane; t < n; t += 32) s_nbr[wid][t] = g_nbrL[i][t];
    __syncwarp();

    const float4* Zb = (const float4*)g_Z;       // rows of 128 float4
    float4 zi[4];
#pragma unroll
    for (int q = 0; q < 4; q++) zi[q] = Zb[(size_t)i * 128 + q * 32 + lane];

    float4 acc[4];
    float  mx[4], sm[4];
#pragma unroll
    for (int q = 0; q < 4; q++) {
        acc[q] = make_float4(0.f, 0.f, 0.f, 0.f);
        mx[q] = -1e30f;
        sm[q] = 0.f;
    }

    float4 b0[4], b1[4];
    {
        int j0 = s_nbr[wid][0];
        int j1 = s_nbr[wid][n > 1 ? 1 : 0];
#pragma unroll
        for (int q = 0; q < 4; q++) {
            b0[q] = Zb[(size_t)j0 * 128 + q * 32 + lane];
            b1[q] = Zb[(size_t)j1 * 128 + q * 32 + lane];
        }
    }

    for (int jj = 0; jj < n; jj += 2) {
        float4 z0[4], z1[4];
#pragma unroll
        for (int q = 0; q < 4; q++) { z0[q] = b0[q]; z1[q] = b1[q]; }
        if (jj + 2 < n) {
            int ja = s_nbr[wid][jj + 2];
#pragma unroll
            for (int q = 0; q < 4; q++) b0[q] = Zb[(size_t)ja * 128 + q * 32 + lane];
        }
        if (jj + 3 < n) {
            int jb = s_nbr[wid][jj + 3];
#pragma unroll
            for (int q = 0; q < 4; q++) b1[q] = Zb[(size_t)jb * 128 + q * 32 + lane];
        }
        const bool have1 = (jj + 1 < n);

        float p0[4], p1[4];
#pragma unroll
        for (int q = 0; q < 4; q++) {
            p0[q] = zi[q].x * z0[q].x + zi[q].y * z0[q].y + zi[q].z * z0[q].z + zi[q].w * z0[q].w;
            p1[q] = zi[q].x * z1[q].x + zi[q].y * z1[q].y + zi[q].z * z1[q].z + zi[q].w * z1[q].w;
        }
#pragma unroll
        for (int o = 1; o < 16; o <<= 1) {
#pragma unroll
            for (int q = 0; q < 4; q++) {
                p0[q] += __shfl_xor_sync(0xffffffffu, p0[q], o);
                p1[q] += __shfl_xor_sync(0xffffffffu, p1[q], o);
            }
        }

#pragma unroll
        for (int q = 0; q < 4; q++) {
            float sc = p0[q] * 0.125f;
            float mn = fmaxf(mx[q], sc);
            float f  = __expf(mx[q] - mn);
            float e  = __expf(sc - mn);
            mx[q] = mn;
            sm[q] = fmaf(sm[q], f, e);
            acc[q].x = fmaf(acc[q].x, f, e * z0[q].x);
            acc[q].y = fmaf(acc[q].y, f, e * z0[q].y);
            acc[q].z = fmaf(acc[q].z, f, e * z0[q].z);
            acc[q].w = fmaf(acc[q].w, f, e * z0[q].w);
        }
        if (have1) {
#pragma unroll
            for (int q = 0; q < 4; q++) {
                float sc = p1[q] * 0.125f;
                float mn = fmaxf(mx[q], sc);
                float f  = __expf(mx[q] - mn);
                float e  = __expf(sc - mn);
                mx[q] = mn;
                sm[q] = fmaf(sm[q], f, e);
                acc[q].x = fmaf(acc[q].x, f, e * z1[q].x);
                acc[q].y = fmaf(acc[q].y, f, e * z1[q].y);
                acc[q].z = fmaf(acc[q].z, f, e * z1[q].z);
                acc[q].w = fmaf(acc[q].w, f, e * z1[q].w);
            }
        }
    }

#pragma unroll
    for (int q = 0; q < 4; q++) {
        float inv = 1.f / sm[q];
        int col = q * 128 + lane * 4;
        __half h0, l0, h1, l1, h2, l2, h3, l3;
        split_f16(acc[q].x * inv, h0, l0);
        split_f16(acc[q].y * inv, h1, l1);
        split_f16(acc[q].z * inv, h2, l2);
        split_f16(acc[q].w * inv, h3, l3);
        ushort4 ph = make_ushort4(__half_as_ushort(h0), __half_as_ushort(h1),
                                  __half_as_ushort(h2), __half_as_ushort(h3));
        ushort4 pl = make_ushort4(__half_as_ushort(l0), __half_as_ushort(l1),
                                  __half_as_ushort(l2), __half_as_ushort(l3));
        *(ushort4*)&g_A1h[(size_t)i * DIM + col] = ph;
        *(ushort4*)&g_A1l[(size_t)i * DIM + col] = pl;
    }
}

// ---------------- orthogonality loss: 28 pairs x 4 (r,s)-quadrants ----------
__global__ void __launch_bounds__(256)
orth_kernel(const float* __restrict__ U, float* __restrict__ out) {
    int b = blockIdx.x;   // 0..27
    int k = 0, l = 1;
    {
        int c = b;
#pragma unroll
        for (int kk = 0; kk < 8; kk++) {
            int row = 7 - kk;
            if (c < row) { k = kk; l = kk + 1 + c; break; }
            c -= row;
        }
    }
    const int quad = blockIdx.y;          // 0..3
    const int rq = (quad >> 1) * 32;
    const int sq = (quad & 1) * 32;

    __shared__ float su[32][33];
    __shared__ float sv[32][33];
    const int tid = threadIdx.x;
    const int tr = tid >> 4, tc = tid & 15;   // 16x16 threads, 2x2 each
    float g[2][2] = {};
    const float* Uk = U + (size_t)k * DIM * 64;
    const float* Ul = U + (size_t)l * DIM * 64;
    for (int d0 = 0; d0 < DIM; d0 += 32) {
#pragma unroll
        for (int it = 0; it < 4; it++) {
            int lin = it * 256 + tid;
            int dd = lin >> 5, r = lin & 31;
            su[dd][r] = Uk[(size_t)(d0 + dd) * 64 + rq + r];
            sv[dd][r] = Ul[(size_t)(d0 + dd) * 64 + sq + r];
        }
        __syncthreads();
#pragma unroll 8
        for (int dd = 0; dd < 32; dd++) {
            float a0 = su[dd][tr * 2], a1 = su[dd][tr * 2 + 1];
            float b0 = sv[dd][tc * 2], b1 = sv[dd][tc * 2 + 1];
            g[0][0] = fmaf(a0, b0, g[0][0]);
            g[0][1] = fmaf(a0, b1, g[0][1]);
            g[1][0] = fmaf(a1, b0, g[1][0]);
            g[1][1] = fmaf(a1, b1, g[1][1]);
        }
        __syncthreads();
    }
    float s = g[0][0] * g[0][0] + g[0][1] * g[0][1] + g[1][0] * g[1][0] + g[1][1] * g[1][1];
#pragma unroll
    for (int o = 16; o; o >>= 1) s += __shfl_xor_sync(0xffffffffu, s, o);
    __shared__ float wsum[8];
    if ((tid & 31) == 0) wsum[tid >> 5] = s;
    __syncthreads();
    if (tid < 8) {
        float t = wsum[tid];
#pragma unroll
        for (int o = 4; o; o >>= 1) t += __shfl_xor_sync(0xffu, t, o);
        if (tid == 0) atomicAdd(out, t);
    }
}

// ---------------- launch: fork-join stream overlap (R11 schedule) -----------
extern "C" void kernel_launch(void* const* d_in, const int* in_sizes, int n_in,
                              void* d_out, int out_size) {
    const float* H   = (const float*)d_in[0];   // [4096, 512]
    const float* adj = (const float*)d_in[1];   // [4096, 4096]
    const float* U   = (const float*)d_in[2];   // [8, 512, 64]
    const float* thr = (const float*)d_in[3];   // [512]
    float* out = (float*)d_out;

    float* orth_ptr = (out_size > NROWS * DIM) ? (out + (size_t)NROWS * DIM) : nullptr;

    static cudaStream_t sB = nullptr, sC = nullptr;
    static cudaEvent_t evRoot = nullptr, evScan = nullptr, evOrth = nullptr, evRep = nullptr;
    if (!sB) {
        cudaStreamCreateWithFlags(&sB, cudaStreamNonBlocking);
        cudaStreamCreateWithFlags(&sC, cudaStreamNonBlocking);
        cudaEventCreateWithFlags(&evRoot, cudaEventDisableTiming);
        cudaEventCreateWithFlags(&evScan, cudaEventDisableTiming);
        cudaEventCreateWithFlags(&evOrth, cudaEventDisableTiming);
        cudaEventCreateWithFlags(&evRep,  cudaEventDisableTiming);
        cudaFuncSetAttribute(hmma_gemm<0>, cudaFuncAttributeMaxDynamicSharedMemorySize, GEMM_SMEM);
        cudaFuncSetAttribute(hmma_gemm<1>, cudaFuncAttributeMaxDynamicSharedMemorySize, GEMM_SMEM);
    }

    // fork
    cudaEventRecord(evRoot, 0);
    cudaStreamWaitEvent(sB, evRoot, 0);
    scan_kernel<<<NROWS, 256, 0, sB>>>(adj);
    cudaEventRecord(evScan, sB);

    cudaStreamWaitEvent(sC, evRoot, 0);
    repack_kernel<<<dim3(2, 16, 8), 256, 0, sC>>>(U);
    cudaEventRecord(evRep, sC);
    if (orth_ptr) {
        zero_kernel<<<1, 1, 0, sC>>>(orth_ptr);
        orth_kernel<<<dim3(28, 4), 256, 0, sC>>>(U, orth_ptr);
        cudaEventRecord(evOrth, sC);
    }

    // main chain on origin stream
    convert_h_kernel<<<(NROWS * DIM / 4 + 255) / 256, 256>>>(H);
    cudaStreamWaitEvent(0, evRep, 0);           // B0 ready for gemm0
    hmma_gemm<0><<<dim3(DIM / 128, NROWS / 64), 256, GEMM_SMEM>>>(nullptr, nullptr, nullptr);
    cudaStreamWaitEvent(0, evScan, 0);          // neighbor lists ready
    attn_kernel<<<NROWS / WPC, 128>>>();
    hmma_gemm<1><<<dim3(DIM / 128, NROWS / 64), 256, GEMM_SMEM>>>(out, H, thr);
    if (orth_ptr) cudaStreamWaitEvent(0, evOrth, 0);
}

// round 15
// speedup vs baseline: 2.4378x; 2.4378x over previous
#include <cuda_runtime.h>
#include <cuda_fp16.h>
#include <cstdint>

#define NROWS 4096
#define DIM   512
#define KH    8
#define WPC   4      /* rows (warps) per attention CTA */
#define MAXW  96     /* max neighbors per row (mean 42, sd 6.4 -> 8 sigma) */

// ---------------- scratch (device globals; no allocations allowed) ----------
__device__ __align__(256) float   g_Z[(size_t)NROWS * DIM];   // Z fp32 [i][c]
__device__ __align__(256) __half  g_Hh[NROWS * DIM];          // H fp16 hi [i][d]
__device__ __align__(256) __half  g_Hl[NROWS * DIM];          // H fp16 lo
__device__ __align__(256) __half  g_A1h[NROWS * DIM];         // Zagg fp16 hi [i][c]
__device__ __align__(256) __half  g_A1l[NROWS * DIM];         // Zagg fp16 lo
__device__ __align__(256) __half  g_B0[DIM * DIM];            // gemm0 B fp16: [c][d]
__device__ __align__(256) __half  g_B1[DIM * DIM];            // gemm1 B fp16: [d][c]
__device__ int g_cnt[NROWS];
__device__ int g_nbrL[NROWS][MAXW];

// ---------------- helpers ----------------------------------------------------
__device__ __forceinline__ uint32_t smem_to_u32(const void* p) {
    uint32_t a;
    asm("{ .reg .u64 t; cvta.to.shared.u64 t, %1; cvt.u32.u64 %0, t; }" : "=r"(a) : "l"(p));
    return a;
}
__device__ __forceinline__ void ldsm_x4(uint32_t* r, uint32_t addr) {
    asm volatile("ldmatrix.sync.aligned.m8n8.x4.shared.b16 {%0,%1,%2,%3}, [%4];"
                 : "=r"(r[0]), "=r"(r[1]), "=r"(r[2]), "=r"(r[3]) : "r"(addr));
}
__device__ __forceinline__ void mma16816(float* c, const uint32_t* a, const uint32_t* b) {
    asm volatile(
        "mma.sync.aligned.m16n8k16.row.col.f32.f16.f16.f32 "
        "{%0,%1,%2,%3}, {%4,%5,%6,%7}, {%8,%9}, {%0,%1,%2,%3};"
        : "+f"(c[0]), "+f"(c[1]), "+f"(c[2]), "+f"(c[3])
        : "r"(a[0]), "r"(a[1]), "r"(a[2]), "r"(a[3]), "r"(b[0]), "r"(b[1]));
}
__device__ __forceinline__ void cp16(uint32_t saddr, const void* g) {
    asm volatile("cp.async.cg.shared.global [%0], [%1], 16;" :: "r"(saddr), "l"(g));
}
#define CP_COMMIT() asm volatile("cp.async.commit_group;" ::: "memory")
#define CP_WAIT1()  asm volatile("cp.async.wait_group 1;" ::: "memory")
#define CP_WAIT0()  asm volatile("cp.async.wait_group 0;" ::: "memory")

__device__ __forceinline__ void split_f16(float v, __half& h, __half& l) {
    h = __float2half_rn(v);
    l = __float2half_rn(v - __half2float(h));
}

// ---------------- adjacency scan -> compact neighbor lists ------------------
__global__ void __launch_bounds__(256)
scan_kernel(const float* __restrict__ adj) {
    __shared__ int wsum[8], wpre[8];
    const int i = blockIdx.x;
    const int tid = threadIdx.x, lane = tid & 31, wid = tid >> 5;
    const float4* arow = (const float4*)(adj + (size_t)i * NROWS);

    float4 v0 = arow[tid * 4 + 0];
    float4 v1 = arow[tid * 4 + 1];
    float4 v2 = arow[tid * 4 + 2];
    float4 v3 = arow[tid * 4 + 3];
    uint32_t flags = 0;
    flags |= (v0.x != 0.f ?     1u : 0u) | (v0.y != 0.f ?     2u : 0u) |
             (v0.z != 0.f ?     4u : 0u) | (v0.w != 0.f ?     8u : 0u);
    flags |= (v1.x != 0.f ?  0x10u : 0u) | (v1.y != 0.f ?  0x20u : 0u) |
             (v1.z != 0.f ?  0x40u : 0u) | (v1.w != 0.f ?  0x80u : 0u);
    flags |= (v2.x != 0.f ? 0x100u : 0u) | (v2.y != 0.f ? 0x200u : 0u) |
             (v2.z != 0.f ? 0x400u : 0u) | (v2.w != 0.f ? 0x800u : 0u);
    flags |= (v3.x != 0.f ? 0x1000u : 0u) | (v3.y != 0.f ? 0x2000u : 0u) |
             (v3.z != 0.f ? 0x4000u : 0u) | (v3.w != 0.f ? 0x8000u : 0u);
    int cnt = __popc(flags);

    int pos = cnt;
#pragma unroll
    for (int o = 1; o < 32; o <<= 1) {
        int t = __shfl_up_sync(0xffffffffu, pos, o);
        if (lane >= o) pos += t;
    }
    if (lane == 31) wsum[wid] = pos;
    __syncthreads();
    if (tid == 0) {
        int a = 0;
#pragma unroll
        for (int w = 0; w < 8; w++) { wpre[w] = a; a += wsum[w]; }
        g_cnt[i] = a < MAXW ? a : MAXW;
    }
    __syncthreads();
    int p = wpre[wid] + pos - cnt;          // exclusive prefix across CTA
    uint32_t m = flags;
    while (m) {
        int b = __ffs(m) - 1; m &= m - 1;
        if (p < MAXW) g_nbrL[i][p] = tid * 16 + b;
        p++;
    }
}

// ---------------- repack U -> B0 (transposed) and B1 (copy), smem-tiled -----
__global__ void __launch_bounds__(256)
repack_kernel(const float* __restrict__ U) {
    __shared__ __half tile[32][33];
    const int kt = blockIdx.x;        // r-tile: 0..1
    const int dt = blockIdx.y;        // d-tile: 0..15
    const int k  = blockIdx.z;        // head:   0..7
    const int tx = threadIdx.x & 31, ty = threadIdx.x >> 5;   // 32 x 8

    const float* Uk = U + (size_t)k * 32768;
#pragma unroll
    for (int i = 0; i < 4; i++) {
        int dd = ty + i * 8;
        int d  = dt * 32 + dd;
        int r  = kt * 32 + tx;
        __half h = __float2half_rn(Uk[d * 64 + r]);
        g_B1[(d << 9) + k * 64 + r] = h;           // coalesced
        tile[dd][tx] = h;
    }
    __syncthreads();
#pragma unroll
    for (int i = 0; i < 4; i++) {
        int cc = ty + i * 8;
        int c  = k * 64 + kt * 32 + cc;
        g_B0[(c << 9) + dt * 32 + tx] = tile[tx][cc];   // coalesced
    }
}

// ---------------- split H into fp16 hi/lo (4 float4 per thread) --------------
__global__ void __launch_bounds__(256)
convert_h_kernel(const float* __restrict__ H) {
    int base = blockIdx.x * 1024 + threadIdx.x;     // float4 index, stride 256
#pragma unroll
    for (int it = 0; it < 4; it++) {
        int i4 = base + it * 256;
        float4 v = ((const float4*)H)[i4];
        __half h0, l0, h1, l1, h2, l2, h3, l3;
        split_f16(v.x, h0, l0); split_f16(v.y, h1, l1);
        split_f16(v.z, h2, l2); split_f16(v.w, h3, l3);
        ushort4 ph = make_ushort4(__half_as_ushort(h0), __half_as_ushort(h1),
                                  __half_as_ushort(h2), __half_as_ushort(h3));
        ushort4 pl = make_ushort4(__half_as_ushort(l0), __half_as_ushort(l1),
                                  __half_as_ushort(l2), __half_as_ushort(l3));
        ((ushort4*)g_Hh)[i4] = ph;
        ((ushort4*)g_Hl)[i4] = pl;
    }
}

// ---------------- zero orth scalar -------------------------------------------
__global__ void zero_kernel(float* p) { *p = 0.f; }

// ---------------- HMMA GEMM: 64x128 CTA tile, K=512, fp16 2-term split ------
// TWO-stage cp.async pipeline (known-good config).
#define GEMM_STAGE 32768            /* Ah 8K | Al 8K | B 16K */
#define GEMM_SMEM  (2 * GEMM_STAGE)
template <int MODE>
__global__ void __launch_bounds__(256, 2)
hmma_gemm(float* __restrict__ Cout, const float* __restrict__ Hin,
          const float* __restrict__ thr) {
    extern __shared__ __align__(1024) char smem[];
    const uint32_t sb = smem_to_u32(smem);
    const int tid  = threadIdx.x;
    const int wid  = tid >> 5, lane = tid & 31;
    const int bm   = blockIdx.y * 64, bn = blockIdx.x * 128;
    const int wm   = (wid >> 2) * 32;
    const int wn   = (wid & 3) * 32;

    const __half* Ah = (MODE == 0) ? g_Hh : g_A1h;
    const __half* Al = (MODE == 0) ? g_Hl : g_A1l;
    const __half* Bm = (MODE == 0) ? g_B0 : g_B1;

    float acc[2][4][4];
#pragma unroll
    for (int a = 0; a < 2; a++)
#pragma unroll
        for (int b = 0; b < 4; b++)
#pragma unroll
            for (int e = 0; e < 4; e++) acc[a][b][e] = 0.f;

    const int aRow = (lane & 15);
    const int aKb  = (lane >> 4) * 16;
    const int bRow = (lane & 7) + ((lane >> 4) << 3);
    const int bKb  = ((lane >> 3) & 1) * 16;

#define STAGE(KC, BUF) do {                                                   \
        const int k0s = (KC) * 64;                                            \
        uint32_t sbase = sb + (BUF) * GEMM_STAGE;                             \
        _Pragma("unroll")                                                     \
        for (int it = 0; it < 2; it++) {                                      \
            int idx = it * 256 + tid;                                         \
            int row = idx >> 3, c16 = idx & 7;                                \
            uint32_t off = (uint32_t)row * 128 + c16 * 16;                    \
            uint32_t sw  = off ^ ((off >> 3) & 0x70);                         \
            size_t g = (size_t)(bm + row) * DIM + k0s + c16 * 8;              \
            cp16(sbase +        sw, Ah + g);                                  \
            cp16(sbase + 8192 + sw, Al + g);                                  \
        }                                                                     \
        _Pragma("unroll")                                                     \
        for (int it = 0; it < 4; it++) {                                      \
            int idx = it * 256 + tid;                                         \
            int row = idx >> 3, c16 = idx & 7;                                \
            uint32_t off = (uint32_t)row * 128 + c16 * 16;                    \
            uint32_t sw  = off ^ ((off >> 3) & 0x70);                         \
            size_t g = (size_t)(bn + row) * DIM + k0s + c16 * 8;              \
            cp16(sbase + 16384 + sw, Bm + g);                                 \
        }                                                                     \
    } while (0)

    STAGE(0, 0); CP_COMMIT();

    for (int kc = 0; kc < 8; kc++) {
        if (kc < 7) { STAGE(kc + 1, (kc + 1) & 1); CP_COMMIT(); CP_WAIT1(); }
        else        { CP_WAIT0(); }
        __syncthreads();
        const uint32_t sbase = sb + (kc & 1) * GEMM_STAGE;
#pragma unroll
        for (int ks = 0; ks < 4; ks++) {
            uint32_t bf[2][4];
#pragma unroll
            for (int g2 = 0; g2 < 2; g2++) {
                uint32_t off = (uint32_t)(wn + g2 * 16 + bRow) * 128 + ks * 32 + bKb;
                uint32_t sw  = off ^ ((off >> 3) & 0x70);
                ldsm_x4(bf[g2], sbase + 16384 + sw);
            }
#pragma unroll
            for (int mf = 0; mf < 2; mf++) {
                uint32_t ah[4], al[4];
                uint32_t off = (uint32_t)(wm + mf * 16 + aRow) * 128 + ks * 32 + aKb;
                uint32_t sw  = off ^ ((off >> 3) & 0x70);
                ldsm_x4(ah, sbase +        sw);
                ldsm_x4(al, sbase + 8192 + sw);
#pragma unroll
                for (int nf = 0; nf < 4; nf++) {
                    const uint32_t* bp = &bf[nf >> 1][(nf & 1) * 2];
                    mma16816(acc[mf][nf], ah, bp);
                    mma16816(acc[mf][nf], al, bp);
                }
            }
        }
        __syncthreads();
    }
#undef STAGE

#pragma unroll
    for (int mf = 0; mf < 2; mf++) {
#pragma unroll
        for (int nf = 0; nf < 4; nf++) {
            int row = bm + wm + mf * 16 + (lane >> 2);
            int col = bn + wn + nf * 8 + (lane & 3) * 2;
            const float* c = acc[mf][nf];
            if (MODE == 0) {
                *(float2*)&g_Z[(size_t)row * DIM + col]       = make_float2(c[0], c[1]);
                *(float2*)&g_Z[(size_t)(row + 8) * DIM + col] = make_float2(c[2], c[3]);
            } else {
                float2 h0 = *(const float2*)&Hin[(size_t)row * DIM + col];
                float2 h1 = *(const float2*)&Hin[(size_t)(row + 8) * DIM + col];
                float2 t  = *(const float2*)&thr[col];
                float2 o0 = make_float2(fmaxf(h0.x + 0.5f * c[0] - t.x, 0.f),
                                        fmaxf(h0.y + 0.5f * c[1] - t.y, 0.f));
                float2 o1 = make_float2(fmaxf(h1.x + 0.5f * c[2] - t.x, 0.f),
                                        fmaxf(h1.y + 0.5f * c[3] - t.y, 0.f));
                *(float2*)&Cout[(size_t)row * DIM + col]       = o0;
                *(float2*)&Cout[(size_t)(row + 8) * DIM + col] = o1;
            }
        }
    }
}

// ---------------- warp-per-row attention, 2-deep prefetch (R11 known-good) --
__global__ void __launch_bounds__(128, 4)
attn_kernel() {
    __shared__ int s_nbr[WPC][MAXW];

    const int wid = threadIdx.x >> 5, lane = threadIdx.x & 31;
    const int i = blockIdx.x * WPC + wid;
    const int n = g_cnt[i];

    for (int t = lane; t < n; t += 32) s_nbr[wid][t] = g_nbrL[i][t];
    __syncwarp();

    const float4* Zb = (const float4*)g_Z;       // rows of 128 float4
    float4 zi[4];
#pragma unroll
    for (int q = 0; q < 4; q++) zi[q] = Zb[(size_t)i * 128 + q * 32 + lane];

    float4 acc[4];
    float  mx[4], sm[4];
#pragma unroll
    for (int q = 0; q < 4; q++) {
        acc[q] = make_float4(0.f, 0.f, 0.f, 0.f);
        mx[q] = -1e30f;
        sm[q] = 0.f;
    }

    float4 b0[4], b1[4];
    {
        int j0 = s_nbr[wid][0];
        int j1 = s_nbr[wid][n > 1 ? 1 : 0];
#pragma unroll
        for (int q = 0; q < 4; q++) {
            b0[q] = Zb[(size_t)j0 * 128 + q * 32 + lane];
            b1[q] = Zb[(size_t)j1 * 128 + q * 32 + lane];
        }
    }

    for (int jj = 0; jj < n; jj += 2) {
        float4 z0[4], z1[4];
#pragma unroll
        for (int q = 0; q < 4; q++) { z0[q] = b0[q]; z1[q] = b1[q]; }
        if (jj + 2 < n) {
            int ja = s_nbr[wid][jj + 2];
#pragma unroll
            for (int q = 0; q < 4; q++) b0[q] = Zb[(size_t)ja * 128 + q * 32 + lane];
        }
        if (jj + 3 < n) {
            int jb = s_nbr[wid][jj + 3];
#pragma unroll
            for (int q = 0; q < 4; q++) b1[q] = Zb[(size_t)jb * 128 + q * 32 + lane];
        }
        const bool have1 = (jj + 1 < n);

        float p0[4], p1[4];
#pragma unroll
        for (int q = 0; q < 4; q++) {
            p0[q] = zi[q].x * z0[q].x + zi[q].y * z0[q].y + zi[q].z * z0[q].z + zi[q].w * z0[q].w;
            p1[q] = zi[q].x * z1[q].x + zi[q].y * z1[q].y + zi[q].z * z1[q].z + zi[q].w * z1[q].w;
        }
#pragma unroll
        for (int o = 1; o < 16; o <<= 1) {
#pragma unroll
            for (int q = 0; q < 4; q++) {
                p0[q] += __shfl_xor_sync(0xffffffffu, p0[q], o);
                p1[q] += __shfl_xor_sync(0xffffffffu, p1[q], o);
            }
        }

#pragma unroll
        for (int q = 0; q < 4; q++) {
            float sc = p0[q] * 0.125f;
            float mn = fmaxf(mx[q], sc);
            float f  = __expf(mx[q] - mn);
            float e  = __expf(sc - mn);
            mx[q] = mn;
            sm[q] = fmaf(sm[q], f, e);
            acc[q].x = fmaf(acc[q].x, f, e * z0[q].x);
            acc[q].y = fmaf(acc[q].y, f, e * z0[q].y);
            acc[q].z = fmaf(acc[q].z, f, e * z0[q].z);
            acc[q].w = fmaf(acc[q].w, f, e * z0[q].w);
        }
        if (have1) {
#pragma unroll
            for (int q = 0; q < 4; q++) {
                float sc = p1[q] * 0.125f;
                float mn = fmaxf(mx[q], sc);
                float f  = __expf(mx[q] - mn);
                float e  = __expf(sc - mn);
                mx[q] = mn;
                sm[q] = fmaf(sm[q], f, e);
                acc[q].x = fmaf(acc[q].x, f, e * z1[q].x);
                acc[q].y = fmaf(acc[q].y, f, e * z1[q].y);
                acc[q].z = fmaf(acc[q].z, f, e * z1[q].z);
                acc[q].w = fmaf(acc[q].w, f, e * z1[q].w);
            }
        }
    }

#pragma unroll
    for (int q = 0; q < 4; q++) {
        float inv = 1.f / sm[q];
        int col = q * 128 + lane * 4;
        __half h0, l0, h1, l1, h2, l2, h3, l3;
        split_f16(acc[q].x * inv, h0, l0);
        split_f16(acc[q].y * inv, h1, l1);
        split_f16(acc[q].z * inv, h2, l2);
        split_f16(acc[q].w * inv, h3, l3);
        ushort4 ph = make_ushort4(__half_as_ushort(h0), __half_as_ushort(h1),
                                  __half_as_ushort(h2), __half_as_ushort(h3));
        ushort4 pl = make_ushort4(__half_as_ushort(l0), __half_as_ushort(l1),
                                  __half_as_ushort(l2), __half_as_ushort(l3));
        *(ushort4*)&g_A1h[(size_t)i * DIM + col] = ph;
        *(ushort4*)&g_A1l[(size_t)i * DIM + col] = pl;
    }
}

// ---------------- orthogonality loss: 28 pairs x 4 (r,s)-quadrants ----------
__global__ void __launch_bounds__(256)
orth_kernel(const float* __restrict__ U, float* __restrict__ out) {
    int b = blockIdx.x;   // 0..27
    int k = 0, l = 1;
    {
        int c = b;
#pragma unroll
        for (int kk = 0; kk < 8; kk++) {
            int row = 7 - kk;
            if (c < row) { k = kk; l = kk + 1 + c; break; }
            c -= row;
        }
    }
    const int quad = blockIdx.y;          // 0..3
    const int rq = (quad >> 1) * 32;
    const int sq = (quad & 1) * 32;

    __shared__ float su[32][33];
    __shared__ float sv[32][33];
    const int tid = threadIdx.x;
    const int tr = tid >> 4, tc = tid & 15;   // 16x16 threads, 2x2 each
    float g[2][2] = {};
    const float* Uk = U + (size_t)k * DIM * 64;
    const float* Ul = U + (size_t)l * DIM * 64;
    for (int d0 = 0; d0 < DIM; d0 += 32) {
#pragma unroll
        for (int it = 0; it < 4; it++) {
            int lin = it * 256 + tid;
            int dd = lin >> 5, r = lin & 31;
            su[dd][r] = Uk[(size_t)(d0 + dd) * 64 + rq + r];
            sv[dd][r] = Ul[(size_t)(d0 + dd) * 64 + sq + r];
        }
        __syncthreads();
#pragma unroll 8
        for (int dd = 0; dd < 32; dd++) {
            float a0 = su[dd][tr * 2], a1 = su[dd][tr * 2 + 1];
            float b0 = sv[dd][tc * 2], b1 = sv[dd][tc * 2 + 1];
            g[0][0] = fmaf(a0, b0, g[0][0]);
            g[0][1] = fmaf(a0, b1, g[0][1]);
            g[1][0] = fmaf(a1, b0, g[1][0]);
            g[1][1] = fmaf(a1, b1, g[1][1]);
        }
        __syncthreads();
    }
    float s = g[0][0] * g[0][0] + g[0][1] * g[0][1] + g[1][0] * g[1][0] + g[1][1] * g[1][1];
#pragma unroll
    for (int o = 16; o; o >>= 1) s += __shfl_xor_sync(0xffffffffu, s, o);
    __shared__ float wsum[8];
    if ((tid & 31) == 0) wsum[tid >> 5] = s;
    __syncthreads();
    if (tid < 8) {
        float t = wsum[tid];
#pragma unroll
        for (int o = 4; o; o >>= 1) t += __shfl_xor_sync(0xffu, t, o);
        if (tid == 0) atomicAdd(out, t);
    }
}

// ---------------- launch: fork-join stream overlap (R11 schedule) -----------
extern "C" void kernel_launch(void* const* d_in, const int* in_sizes, int n_in,
                              void* d_out, int out_size) {
    const float* H   = (const float*)d_in[0];   // [4096, 512]
    const float* adj = (const float*)d_in[1];   // [4096, 4096]
    const float* U   = (const float*)d_in[2];   // [8, 512, 64]
    const float* thr = (const float*)d_in[3];   // [512]
    float* out = (float*)d_out;

    float* orth_ptr = (out_size > NROWS * DIM) ? (out + (size_t)NROWS * DIM) : nullptr;

    static cudaStream_t sB = nullptr, sC = nullptr;
    static cudaEvent_t evRoot = nullptr, evScan = nullptr, evOrth = nullptr, evRep = nullptr;
    if (!sB) {
        cudaStreamCreateWithFlags(&sB, cudaStreamNonBlocking);
        cudaStreamCreateWithFlags(&sC, cudaStreamNonBlocking);
        cudaEventCreateWithFlags(&evRoot, cudaEventDisableTiming);
        cudaEventCreateWithFlags(&evScan, cudaEventDisableTiming);
        cudaEventCreateWithFlags(&evOrth, cudaEventDisableTiming);
        cudaEventCreateWithFlags(&evRep,  cudaEventDisableTiming);
        cudaFuncSetAttribute(hmma_gemm<0>, cudaFuncAttributeMaxDynamicSharedMemorySize, GEMM_SMEM);
        cudaFuncSetAttribute(hmma_gemm<1>, cudaFuncAttributeMaxDynamicSharedMemorySize, GEMM_SMEM);
    }

    // fork
    cudaEventRecord(evRoot, 0);
    cudaStreamWaitEvent(sB, evRoot, 0);
    scan_kernel<<<NROWS, 256, 0, sB>>>(adj);
    cudaEventRecord(evScan, sB);

    cudaStreamWaitEvent(sC, evRoot, 0);
    repack_kernel<<<dim3(2, 16, 8), 256, 0, sC>>>(U);
    cudaEventRecord(evRep, sC);
    if (orth_ptr) {
        zero_kernel<<<1, 1, 0, sC>>>(orth_ptr);
        orth_kernel<<<dim3(28, 4), 256, 0, sC>>>(U, orth_ptr);
        cudaEventRecord(evOrth, sC);
    }

    // main chain on origin stream
    convert_h_kernel<<<NROWS * DIM / 4 / 1024, 256>>>(H);
    cudaStreamWaitEvent(0, evRep, 0);           // B0 ready for gemm0
    hmma_gemm<0><<<dim3(DIM / 128, NROWS / 64), 256, GEMM_SMEM>>>(nullptr, nullptr, nullptr);
    cudaStreamWaitEvent(0, evScan, 0);          // neighbor lists ready
    attn_kernel<<<NROWS / WPC, 128>>>();
    hmma_gemm<1><<<dim3(DIM / 128, NROWS / 64), 256, GEMM_SMEM>>>(out, H, thr);
    if (orth_ptr) cudaStreamWaitEvent(0, evOrth, 0);
}

// round 16
// speedup vs baseline: 2.4872x; 1.0203x over previous
#include <cuda_runtime.h>
#include <cuda_fp16.h>
#include <cstdint>

#define NROWS 4096
#define DIM   512
#define KH    8
#define WPC   4      /* rows (warps) per attention CTA */
#define MAXW  96     /* max neighbors per row (mean 42, sd 6.4 -> 8 sigma) */

// ---------------- scratch (device globals; no allocations allowed) ----------
__device__ __align__(256) float   g_Z[(size_t)NROWS * DIM];   // Z fp32 [i][c]
__device__ __align__(256) __half  g_Hh[NROWS * DIM];          // H fp16 hi [i][d]
__device__ __align__(256) __half  g_Hl[NROWS * DIM];          // H fp16 lo
__device__ __align__(256) __half  g_A1h[NROWS * DIM];         // Zagg fp16 hi [i][c]
__device__ __align__(256) __half  g_A1l[NROWS * DIM];         // Zagg fp16 lo
__device__ __align__(256) __half  g_B0[DIM * DIM];            // gemm0 B fp16: [c][d]
__device__ __align__(256) __half  g_B1[DIM * DIM];            // gemm1 B fp16: [d][c]
__device__ int g_cnt[NROWS];
__device__ int g_nbrL[NROWS][MAXW];

// ---------------- helpers ----------------------------------------------------
__device__ __forceinline__ uint32_t smem_to_u32(const void* p) {
    uint32_t a;
    asm("{ .reg .u64 t; cvta.to.shared.u64 t, %1; cvt.u32.u64 %0, t; }" : "=r"(a) : "l"(p));
    return a;
}
__device__ __forceinline__ void ldsm_x4(uint32_t* r, uint32_t addr) {
    asm volatile("ldmatrix.sync.aligned.m8n8.x4.shared.b16 {%0,%1,%2,%3}, [%4];"
                 : "=r"(r[0]), "=r"(r[1]), "=r"(r[2]), "=r"(r[3]) : "r"(addr));
}
__device__ __forceinline__ void mma16816(float* c, const uint32_t* a, const uint32_t* b) {
    asm volatile(
        "mma.sync.aligned.m16n8k16.row.col.f32.f16.f16.f32 "
        "{%0,%1,%2,%3}, {%4,%5,%6,%7}, {%8,%9}, {%0,%1,%2,%3};"
        : "+f"(c[0]), "+f"(c[1]), "+f"(c[2]), "+f"(c[3])
        : "r"(a[0]), "r"(a[1]), "r"(a[2]), "r"(a[3]), "r"(b[0]), "r"(b[1]));
}
__device__ __forceinline__ void cp16(uint32_t saddr, const void* g) {
    asm volatile("cp.async.cg.shared.global [%0], [%1], 16;" :: "r"(saddr), "l"(g));
}
#define CP_COMMIT() asm volatile("cp.async.commit_group;" ::: "memory")
#define CP_WAIT1()  asm volatile("cp.async.wait_group 1;" ::: "memory")
#define CP_WAIT0()  asm volatile("cp.async.wait_group 0;" ::: "memory")

__device__ __forceinline__ void split_f16(float v, __half& h, __half& l) {
    h = __float2half_rn(v);
    l = __float2half_rn(v - __half2float(h));
}

// ---------------- adjacency scan -> compact neighbor lists ------------------
__global__ void __launch_bounds__(256)
scan_kernel(const float* __restrict__ adj) {
    __shared__ int wsum[8], wpre[8];
    const int i = blockIdx.x;
    const int tid = threadIdx.x, lane = tid & 31, wid = tid >> 5;
    const float4* arow = (const float4*)(adj + (size_t)i * NROWS);

    float4 v0 = arow[tid * 4 + 0];
    float4 v1 = arow[tid * 4 + 1];
    float4 v2 = arow[tid * 4 + 2];
    float4 v3 = arow[tid * 4 + 3];
    uint32_t flags = 0;
    flags |= (v0.x != 0.f ?     1u : 0u) | (v0.y != 0.f ?     2u : 0u) |
             (v0.z != 0.f ?     4u : 0u) | (v0.w != 0.f ?     8u : 0u);
    flags |= (v1.x != 0.f ?  0x10u : 0u) | (v1.y != 0.f ?  0x20u : 0u) |
             (v1.z != 0.f ?  0x40u : 0u) | (v1.w != 0.f ?  0x80u : 0u);
    flags |= (v2.x != 0.f ? 0x100u : 0u) | (v2.y != 0.f ? 0x200u : 0u) |
             (v2.z != 0.f ? 0x400u : 0u) | (v2.w != 0.f ? 0x800u : 0u);
    flags |= (v3.x != 0.f ? 0x1000u : 0u) | (v3.y != 0.f ? 0x2000u : 0u) |
             (v3.z != 0.f ? 0x4000u : 0u) | (v3.w != 0.f ? 0x8000u : 0u);
    int cnt = __popc(flags);

    int pos = cnt;
#pragma unroll
    for (int o = 1; o < 32; o <<= 1) {
        int t = __shfl_up_sync(0xffffffffu, pos, o);
        if (lane >= o) pos += t;
    }
    if (lane == 31) wsum[wid] = pos;
    __syncthreads();
    if (tid == 0) {
        int a = 0;
#pragma unroll
        for (int w = 0; w < 8; w++) { wpre[w] = a; a += wsum[w]; }
        g_cnt[i] = a < MAXW ? a : MAXW;
    }
    __syncthreads();
    int p = wpre[wid] + pos - cnt;          // exclusive prefix across CTA
    uint32_t m = flags;
    while (m) {
        int b = __ffs(m) - 1; m &= m - 1;
        if (p < MAXW) g_nbrL[i][p] = tid * 16 + b;
        p++;
    }
}

// ---------------- repack U -> B0 (transposed) and B1 (copy), smem-tiled -----
__global__ void __launch_bounds__(256)
repack_kernel(const float* __restrict__ U) {
    __shared__ __half tile[32][33];
    const int kt = blockIdx.x;        // r-tile: 0..1
    const int dt = blockIdx.y;        // d-tile: 0..15
    const int k  = blockIdx.z;        // head:   0..7
    const int tx = threadIdx.x & 31, ty = threadIdx.x >> 5;   // 32 x 8

    const float* Uk = U + (size_t)k * 32768;
#pragma unroll
    for (int i = 0; i < 4; i++) {
        int dd = ty + i * 8;
        int d  = dt * 32 + dd;
        int r  = kt * 32 + tx;
        __half h = __float2half_rn(Uk[d * 64 + r]);
        g_B1[(d << 9) + k * 64 + r] = h;           // coalesced
        tile[dd][tx] = h;
    }
    __syncthreads();
#pragma unroll
    for (int i = 0; i < 4; i++) {
        int cc = ty + i * 8;
        int c  = k * 64 + kt * 32 + cc;
        g_B0[(c << 9) + dt * 32 + tx] = tile[tx][cc];   // coalesced
    }
}

// ---------------- split H into fp16 hi/lo (4 float4 per thread) --------------
__global__ void __launch_bounds__(256)
convert_h_kernel(const float* __restrict__ H) {
    int base = blockIdx.x * 1024 + threadIdx.x;     // float4 index, stride 256
#pragma unroll
    for (int it = 0; it < 4; it++) {
        int i4 = base + it * 256;
        float4 v = ((const float4*)H)[i4];
        __half h0, l0, h1, l1, h2, l2, h3, l3;
        split_f16(v.x, h0, l0); split_f16(v.y, h1, l1);
        split_f16(v.z, h2, l2); split_f16(v.w, h3, l3);
        ushort4 ph = make_ushort4(__half_as_ushort(h0), __half_as_ushort(h1),
                                  __half_as_ushort(h2), __half_as_ushort(h3));
        ushort4 pl = make_ushort4(__half_as_ushort(l0), __half_as_ushort(l1),
                                  __half_as_ushort(l2), __half_as_ushort(l3));
        ((ushort4*)g_Hh)[i4] = ph;
        ((ushort4*)g_Hl)[i4] = pl;
    }
}

// ---------------- zero orth scalar -------------------------------------------
__global__ void zero_kernel(float* p) { *p = 0.f; }

// ---------------- HMMA GEMM: 64x128 CTA tile, K=512, fp16 2-term split ------
// TWO-stage cp.async pipeline (known-good config).
#define GEMM_STAGE 32768            /* Ah 8K | Al 8K | B 16K */
#define GEMM_SMEM  (2 * GEMM_STAGE)
template <int MODE>
__global__ void __launch_bounds__(256, 2)
hmma_gemm(float* __restrict__ Cout, const float* __restrict__ Hin,
          const float* __restrict__ thr) {
    extern __shared__ __align__(1024) char smem[];
    const uint32_t sb = smem_to_u32(smem);
    const int tid  = threadIdx.x;
    const int wid  = tid >> 5, lane = tid & 31;
    const int bm   = blockIdx.y * 64, bn = blockIdx.x * 128;
    const int wm   = (wid >> 2) * 32;
    const int wn   = (wid & 3) * 32;

    const __half* Ah = (MODE == 0) ? g_Hh : g_A1h;
    const __half* Al = (MODE == 0) ? g_Hl : g_A1l;
    const __half* Bm = (MODE == 0) ? g_B0 : g_B1;

    float acc[2][4][4];
#pragma unroll
    for (int a = 0; a < 2; a++)
#pragma unroll
        for (int b = 0; b < 4; b++)
#pragma unroll
            for (int e = 0; e < 4; e++) acc[a][b][e] = 0.f;

    const int aRow = (lane & 15);
    const int aKb  = (lane >> 4) * 16;
    const int bRow = (lane & 7) + ((lane >> 4) << 3);
    const int bKb  = ((lane >> 3) & 1) * 16;

#define STAGE(KC, BUF) do {                                                   \
        const int k0s = (KC) * 64;                                            \
        uint32_t sbase = sb + (BUF) * GEMM_STAGE;                             \
        _Pragma("unroll")                                                     \
        for (int it = 0; it < 2; it++) {                                      \
            int idx = it * 256 + tid;                                         \
            int row = idx >> 3, c16 = idx & 7;                                \
            uint32_t off = (uint32_t)row * 128 + c16 * 16;                    \
            uint32_t sw  = off ^ ((off >> 3) & 0x70);                         \
            size_t g = (size_t)(bm + row) * DIM + k0s + c16 * 8;              \
            cp16(sbase +        sw, Ah + g);                                  \
            cp16(sbase + 8192 + sw, Al + g);                                  \
        }                                                                     \
        _Pragma("unroll")                                                     \
        for (int it = 0; it < 4; it++) {                                      \
            int idx = it * 256 + tid;                                         \
            int row = idx >> 3, c16 = idx & 7;                                \
            uint32_t off = (uint32_t)row * 128 + c16 * 16;                    \
            uint32_t sw  = off ^ ((off >> 3) & 0x70);                         \
            size_t g = (size_t)(bn + row) * DIM + k0s + c16 * 8;              \
            cp16(sbase + 16384 + sw, Bm + g);                                 \
        }                                                                     \
    } while (0)

    STAGE(0, 0); CP_COMMIT();

    for (int kc = 0; kc < 8; kc++) {
        if (kc < 7) { STAGE(kc + 1, (kc + 1) & 1); CP_COMMIT(); CP_WAIT1(); }
        else        { CP_WAIT0(); }
        __syncthreads();
        const uint32_t sbase = sb + (kc & 1) * GEMM_STAGE;
#pragma unroll
        for (int ks = 0; ks < 4; ks++) {
            uint32_t bf[2][4];
#pragma unroll
            for (int g2 = 0; g2 < 2; g2++) {
                uint32_t off = (uint32_t)(wn + g2 * 16 + bRow) * 128 + ks * 32 + bKb;
                uint32_t sw  = off ^ ((off >> 3) & 0x70);
                ldsm_x4(bf[g2], sbase + 16384 + sw);
            }
#pragma unroll
            for (int mf = 0; mf < 2; mf++) {
                uint32_t ah[4], al[4];
                uint32_t off = (uint32_t)(wm + mf * 16 + aRow) * 128 + ks * 32 + aKb;
                uint32_t sw  = off ^ ((off >> 3) & 0x70);
                ldsm_x4(ah, sbase +        sw);
                ldsm_x4(al, sbase + 8192 + sw);
#pragma unroll
                for (int nf = 0; nf < 4; nf++) {
                    const uint32_t* bp = &bf[nf >> 1][(nf & 1) * 2];
                    mma16816(acc[mf][nf], ah, bp);
                    mma16816(acc[mf][nf], al, bp);
                }
            }
        }
        __syncthreads();
    }
#undef STAGE

#pragma unroll
    for (int mf = 0; mf < 2; mf++) {
#pragma unroll
        for (int nf = 0; nf < 4; nf++) {
            int row = bm + wm + mf * 16 + (lane >> 2);
            int col = bn + wn + nf * 8 + (lane & 3) * 2;
            const float* c = acc[mf][nf];
            if (MODE == 0) {
                *(float2*)&g_Z[(size_t)row * DIM + col]       = make_float2(c[0], c[1]);
                *(float2*)&g_Z[(size_t)(row + 8) * DIM + col] = make_float2(c[2], c[3]);
            } else {
                float2 h0 = *(const float2*)&Hin[(size_t)row * DIM + col];
                float2 h1 = *(const float2*)&Hin[(size_t)(row + 8) * DIM + col];
                float2 t  = *(const float2*)&thr[col];
                float2 o0 = make_float2(fmaxf(h0.x + 0.5f * c[0] - t.x, 0.f),
                                        fmaxf(h0.y + 0.5f * c[1] - t.y, 0.f));
                float2 o1 = make_float2(fmaxf(h1.x + 0.5f * c[2] - t.x, 0.f),
                                        fmaxf(h1.y + 0.5f * c[3] - t.y, 0.f));
                *(float2*)&Cout[(size_t)row * DIM + col]       = o0;
                *(float2*)&Cout[(size_t)(row + 8) * DIM + col] = o1;
            }
        }
    }
}

// ---------------- warp-per-row attention, 2-deep prefetch (R11 known-good) --
__global__ void __launch_bounds__(128, 4)
attn_kernel() {
    __shared__ int s_nbr[WPC][MAXW];

    const int wid = threadIdx.x >> 5, lane = threadIdx.x & 31;
    const int i = blockIdx.x * WPC + wid;
    const int n = g_cnt[i];

    for (int t = lane; t < n; t += 32) s_nbr[wid][t] = g_nbrL[i][t];
    __syncwarp();

    const float4* Zb = (const float4*)g_Z;       // rows of 128 float4
    float4 zi[4];
#pragma unroll
    for (int q = 0; q < 4; q++) zi[q] = Zb[(size_t)i * 128 + q * 32 + lane];

    float4 acc[4];
    float  mx[4], sm[4];
#pragma unroll
    for (int q = 0; q < 4; q++) {
        acc[q] = make_float4(0.f, 0.f, 0.f, 0.f);
        mx[q] = -1e30f;
        sm[q] = 0.f;
    }

    float4 b0[4], b1[4];
    {
        int j0 = s_nbr[wid][0];
        int j1 = s_nbr[wid][n > 1 ? 1 : 0];
#pragma unroll
        for (int q = 0; q < 4; q++) {
            b0[q] = Zb[(size_t)j0 * 128 + q * 32 + lane];
            b1[q] = Zb[(size_t)j1 * 128 + q * 32 + lane];
        }
    }

    for (int jj = 0; jj < n; jj += 2) {
        float4 z0[4], z1[4];
#pragma unroll
        for (int q = 0; q < 4; q++) { z0[q] = b0[q]; z1[q] = b1[q]; }
        if (jj + 2 < n) {
            int ja = s_nbr[wid][jj + 2];
#pragma unroll
            for (int q = 0; q < 4; q++) b0[q] = Zb[(size_t)ja * 128 + q * 32 + lane];
        }
        if (jj + 3 < n) {
            int jb = s_nbr[wid][jj + 3];
#pragma unroll
            for (int q = 0; q < 4; q++) b1[q] = Zb[(size_t)jb * 128 + q * 32 + lane];
        }
        const bool have1 = (jj + 1 < n);

        float p0[4], p1[4];
#pragma unroll
        for (int q = 0; q < 4; q++) {
            p0[q] = zi[q].x * z0[q].x + zi[q].y * z0[q].y + zi[q].z * z0[q].z + zi[q].w * z0[q].w;
            p1[q] = zi[q].x * z1[q].x + zi[q].y * z1[q].y + zi[q].z * z1[q].z + zi[q].w * z1[q].w;
        }
#pragma unroll
        for (int o = 1; o < 16; o <<= 1) {
#pragma unroll
            for (int q = 0; q < 4; q++) {
                p0[q] += __shfl_xor_sync(0xffffffffu, p0[q], o);
                p1[q] += __shfl_xor_sync(0xffffffffu, p1[q], o);
            }
        }

#pragma unroll
        for (int q = 0; q < 4; q++) {
            float sc = p0[q] * 0.125f;
            float mn = fmaxf(mx[q], sc);
            float f  = __expf(mx[q] - mn);
            float e  = __expf(sc - mn);
            mx[q] = mn;
            sm[q] = fmaf(sm[q], f, e);
            acc[q].x = fmaf(acc[q].x, f, e * z0[q].x);
            acc[q].y = fmaf(acc[q].y, f, e * z0[q].y);
            acc[q].z = fmaf(acc[q].z, f, e * z0[q].z);
            acc[q].w = fmaf(acc[q].w, f, e * z0[q].w);
        }
        if (have1) {
#pragma unroll
            for (int q = 0; q < 4; q++) {
                float sc = p1[q] * 0.125f;
                float mn = fmaxf(mx[q], sc);
                float f  = __expf(mx[q] - mn);
                float e  = __expf(sc - mn);
                mx[q] = mn;
                sm[q] = fmaf(sm[q], f, e);
                acc[q].x = fmaf(acc[q].x, f, e * z1[q].x);
                acc[q].y = fmaf(acc[q].y, f, e * z1[q].y);
                acc[q].z = fmaf(acc[q].z, f, e * z1[q].z);
                acc[q].w = fmaf(acc[q].w, f, e * z1[q].w);
            }
        }
    }

#pragma unroll
    for (int q = 0; q < 4; q++) {
        float inv = 1.f / sm[q];
        int col = q * 128 + lane * 4;
        __half h0, l0, h1, l1, h2, l2, h3, l3;
        split_f16(acc[q].x * inv, h0, l0);
        split_f16(acc[q].y * inv, h1, l1);
        split_f16(acc[q].z * inv, h2, l2);
        split_f16(acc[q].w * inv, h3, l3);
        ushort4 ph = make_ushort4(__half_as_ushort(h0), __half_as_ushort(h1),
                                  __half_as_ushort(h2), __half_as_ushort(h3));
        ushort4 pl = make_ushort4(__half_as_ushort(l0), __half_as_ushort(l1),
                                  __half_as_ushort(l2), __half_as_ushort(l3));
        *(ushort4*)&g_A1h[(size_t)i * DIM + col] = ph;
        *(ushort4*)&g_A1l[(size_t)i * DIM + col] = pl;
    }
}

// ---------------- orthogonality loss: 28 pairs x 4 (r,s)-quadrants ----------
__global__ void __launch_bounds__(256)
orth_kernel(const float* __restrict__ U, float* __restrict__ out) {
    int b = blockIdx.x;   // 0..27
    int k = 0, l = 1;
    {
        int c = b;
#pragma unroll
        for (int kk = 0; kk < 8; kk++) {
            int row = 7 - kk;
            if (c < row) { k = kk; l = kk + 1 + c; break; }
            c -= row;
        }
    }
    const int quad = blockIdx.y;          // 0..3
    const int rq = (quad >> 1) * 32;
    const int sq = (quad & 1) * 32;

    __shared__ float su[32][33];
    __shared__ float sv[32][33];
    const int tid = threadIdx.x;
    const int tr = tid >> 4, tc = tid & 15;   // 16x16 threads, 2x2 each
    float g[2][2] = {};
    const float* Uk = U + (size_t)k * DIM * 64;
    const float* Ul = U + (size_t)l * DIM * 64;
    for (int d0 = 0; d0 < DIM; d0 += 32) {
#pragma unroll
        for (int it = 0; it < 4; it++) {
            int lin = it * 256 + tid;
            int dd = lin >> 5, r = lin & 31;
            su[dd][r] = Uk[(size_t)(d0 + dd) * 64 + rq + r];
            sv[dd][r] = Ul[(size_t)(d0 + dd) * 64 + sq + r];
        }
        __syncthreads();
#pragma unroll 8
        for (int dd = 0; dd < 32; dd++) {
            float a0 = su[dd][tr * 2], a1 = su[dd][tr * 2 + 1];
            float b0 = sv[dd][tc * 2], b1 = sv[dd][tc * 2 + 1];
            g[0][0] = fmaf(a0, b0, g[0][0]);
            g[0][1] = fmaf(a0, b1, g[0][1]);
            g[1][0] = fmaf(a1, b0, g[1][0]);
            g[1][1] = fmaf(a1, b1, g[1][1]);
        }
        __syncthreads();
    }
    float s = g[0][0] * g[0][0] + g[0][1] * g[0][1] + g[1][0] * g[1][0] + g[1][1] * g[1][1];
#pragma unroll
    for (int o = 16; o; o >>= 1) s += __shfl_xor_sync(0xffffffffu, s, o);
    __shared__ float wsum[8];
    if ((tid & 31) == 0) wsum[tid >> 5] = s;
    __syncthreads();
    if (tid < 8) {
        float t = wsum[tid];
#pragma unroll
        for (int o = 4; o; o >>= 1) t += __shfl_xor_sync(0xffu, t, o);
        if (tid == 0) atomicAdd(out, t);
    }
}

// ---------------- launch: fork-join stream overlap (R11 schedule) -----------
extern "C" void kernel_launch(void* const* d_in, const int* in_sizes, int n_in,
                              void* d_out, int out_size) {
    const float* H   = (const float*)d_in[0];   // [4096, 512]
    const float* adj = (const float*)d_in[1];   // [4096, 4096]
    const float* U   = (const float*)d_in[2];   // [8, 512, 64]
    const float* thr = (const float*)d_in[3];   // [512]
    float* out = (float*)d_out;

    float* orth_ptr = (out_size > NROWS * DIM) ? (out + (size_t)NROWS * DIM) : nullptr;

    static cudaStream_t sB = nullptr, sC = nullptr;
    static cudaEvent_t evRoot = nullptr, evScan = nullptr, evOrth = nullptr, evRep = nullptr;
    if (!sB) {
        cudaStreamCreateWithFlags(&sB, cudaStreamNonBlocking);
        cudaStreamCreateWithFlags(&sC, cudaStreamNonBlocking);
        cudaEventCreateWithFlags(&evRoot, cudaEventDisableTiming);
        cudaEventCreateWithFlags(&evScan, cudaEventDisableTiming);
        cudaEventCreateWithFlags(&evOrth, cudaEventDisableTiming);
        cudaEventCreateWithFlags(&evRep,  cudaEventDisableTiming);
        cudaFuncSetAttribute(hmma_gemm<0>, cudaFuncAttributeMaxDynamicSharedMemorySize, GEMM_SMEM);
        cudaFuncSetAttribute(hmma_gemm<1>, cudaFuncAttributeMaxDynamicSharedMemorySize, GEMM_SMEM);
    }

    // fork
    cudaEventRecord(evRoot, 0);
    cudaStreamWaitEvent(sB, evRoot, 0);
    scan_kernel<<<NROWS, 256, 0, sB>>>(adj);
    cudaEventRecord(evScan, sB);

    cudaStreamWaitEvent(sC, evRoot, 0);
    repack_kernel<<<dim3(2, 16, 8), 256, 0, sC>>>(U);
    cudaEventRecord(evRep, sC);
    if (orth_ptr) {
        zero_kernel<<<1, 1, 0, sC>>>(orth_ptr);
        orth_kernel<<<dim3(28, 4), 256, 0, sC>>>(U, orth_ptr);
        cudaEventRecord(evOrth, sC);
    }

    // main chain on origin stream
    convert_h_kernel<<<NROWS * DIM / 4 / 1024, 256>>>(H);
    cudaStreamWaitEvent(0, evRep, 0);           // B0 ready for gemm0
    hmma_gemm<0><<<dim3(DIM / 128, NROWS / 64), 256, GEMM_SMEM>>>(nullptr, nullptr, nullptr);
    cudaStreamWaitEvent(0, evScan, 0);          // neighbor lists ready
    attn_kernel<<<NROWS / WPC, 128>>>();
    hmma_gemm<1><<<dim3(DIM / 128, NROWS / 64), 256, GEMM_SMEM>>>(out, H, thr);
    if (orth_ptr) cudaStreamWaitEvent(0, evOrth, 0);
}